// round 9
// baseline (speedup 1.0000x reference)
#include <cuda_runtime.h>
#include <cstdint>

#define M_TOK   100352      // 32 * 56 * 56
#define DIM     256
#define QKV_N   768
#define HEADS   8
#define HD      32
#define WS      7
#define NT      49
#define SCALE   0.17677669529663687f

// Scratch (device globals: allocation-free per harness rules)
__device__ float g_qkv[(size_t)M_TOK * QKV_N];   // 308 MB
__device__ float g_attn[(size_t)M_TOK * DIM];    // k-permuted + tf32-rounded
__device__ float g_xtf[(size_t)M_TOK * DIM];     // k-permuted + tf32-rounded x
__device__ float g_bias[NT * NT];
__device__ float g_wqkvT[QKV_N * DIM];           // transposed + k-permuted + rounded
__device__ float g_woutT[DIM * DIM];             // transposed + k-permuted + rounded

// k-storage permutation within each 8-group: logical k -> storage
// sigma(k) = (k & ~7) | ((k&3)<<1) | ((k>>2)&1)
// so fragment pair (kc, kc+4) sits at adjacent storage words (LDS.64).

__device__ __forceinline__ uint32_t f2tf32(float f) {
    uint32_t r;
    asm("cvt.rna.tf32.f32 %0, %1;" : "=r"(r) : "f"(f));
    return r;
}
__device__ __forceinline__ float rnd(float f) { return __uint_as_float(f2tf32(f)); }
__device__ __forceinline__ uint32_t smem_u32(const void* p) {
    uint32_t a;
    asm("{ .reg .u64 t; cvta.to.shared.u64 t, %1; cvt.u32.u64 %0, t; }"
        : "=r"(a) : "l"(p));
    return a;
}
__device__ __forceinline__ void cpasync16(uint32_t dst, const void* src) {
    asm volatile("cp.async.ca.shared.global [%0], [%1], 16;"
                 :: "r"(dst), "l"(src));
}
__device__ __forceinline__ void mma_tf32(float* c, uint32_t a0, uint32_t a1,
                                         uint32_t a2, uint32_t a3,
                                         uint32_t b0, uint32_t b1) {
    asm volatile(
        "mma.sync.aligned.m16n8k8.row.col.f32.tf32.tf32.f32 "
        "{%0,%1,%2,%3}, {%4,%5,%6,%7}, {%8,%9}, {%0,%1,%2,%3};"
        : "+f"(c[0]), "+f"(c[1]), "+f"(c[2]), "+f"(c[3])
        : "r"(a0), "r"(a1), "r"(a2), "r"(a3), "r"(b0), "r"(b1));
}

// ---------------------------------------------------------------------------
// tf32 mma.sync GEMM, cp.async 2-stage pipeline, k-permuted inputs,
// LDS.64 fragment loads. Stride 40 -> conflict-free 64-bit half-warp phases.
// ---------------------------------------------------------------------------
#define TSTR 40
#define TILEF (128 * TSTR)
#define TILEB (TILEF * 4)

__global__ __launch_bounds__(256, 2) void mma_gemm(
    const float* __restrict__ A, const float* __restrict__ BT,
    float* __restrict__ C, const float* __restrict__ bias,
    int N, int K)
{
    extern __shared__ float sm[];
    const uint32_t smbase = smem_u32(sm);

    const int tid  = threadIdx.x;
    const int wid  = tid >> 5;
    const int lane = tid & 31;
    const int group = lane >> 2;
    const int tig   = lane & 3;
    const int m0w = (wid & 1) * 64;
    const int n0w = (wid >> 1) * 32;
    const int bm = blockIdx.y * 128;
    const int bn = blockIdx.x * 128;

    const int lrow = tid >> 3;
    const int lcf4 = tid & 7;

    float c[4][4][4];
#pragma unroll
    for (int mt = 0; mt < 4; mt++)
#pragma unroll
        for (int nt = 0; nt < 4; nt++)
#pragma unroll
            for (int r = 0; r < 4; r++) c[mt][nt][r] = 0.f;

    const int nch = K >> 5;
    const uint32_t doff0 = (uint32_t)(lrow * TSTR + lcf4 * 4) * 4;

    auto issue = [&](int cc, int b) {
        const int k0 = cc * 32;
        const uint32_t aBase = smbase + (uint32_t)b * 2 * TILEB + doff0;
        const uint32_t bBase = aBase + TILEB;
#pragma unroll
        for (int i = 0; i < 4; i++) {
            const int row = lrow + 32 * i;
            cpasync16(aBase + (uint32_t)i * 32 * TSTR * 4,
                      &A[(size_t)(bm + row) * K + k0 + lcf4 * 4]);
            cpasync16(bBase + (uint32_t)i * 32 * TSTR * 4,
                      &BT[(size_t)(bn + row) * K + k0 + lcf4 * 4]);
        }
    };

    issue(0, 0);
    asm volatile("cp.async.commit_group;");
    if (nch > 1) issue(1, 1);
    asm volatile("cp.async.commit_group;");

    for (int cidx = 0; cidx < nch; cidx++) {
        const int buf = cidx & 1;
        asm volatile("cp.async.wait_group 1;");
        __syncthreads();

        const uint32_t* As = (const uint32_t*)(sm + buf * 2 * TILEF);
        const uint32_t* Bs = (const uint32_t*)(sm + buf * 2 * TILEF + TILEF);
#pragma unroll
        for (int k8 = 0; k8 < 4; k8++) {
            const int kp = k8 * 8 + 2 * tig;   // permuted: (kc, kc+4) adjacent
            uint32_t a[4][4], b[4][2];
#pragma unroll
            for (int mt = 0; mt < 4; mt++) {
                const int r0 = m0w + mt * 16 + group;
                uint2 lo = *(const uint2*)&As[r0 * TSTR + kp];
                uint2 hi = *(const uint2*)&As[(r0 + 8) * TSTR + kp];
                a[mt][0] = lo.x; a[mt][2] = lo.y;
                a[mt][1] = hi.x; a[mt][3] = hi.y;
            }
#pragma unroll
            for (int nt = 0; nt < 4; nt++) {
                const int r0 = n0w + nt * 8 + group;
                uint2 bb = *(const uint2*)&Bs[r0 * TSTR + kp];
                b[nt][0] = bb.x; b[nt][1] = bb.y;
            }
#pragma unroll
            for (int mt = 0; mt < 4; mt++)
#pragma unroll
                for (int nt = 0; nt < 4; nt++)
                    mma_tf32(c[mt][nt], a[mt][0], a[mt][1], a[mt][2], a[mt][3],
                             b[nt][0], b[nt][1]);
        }
        __syncthreads();
        if (cidx + 2 < nch) issue(cidx + 2, buf);
        asm volatile("cp.async.commit_group;");
    }

#pragma unroll
    for (int nt = 0; nt < 4; nt++) {
        const int col = bn + n0w + nt * 8 + tig * 2;
        float bv0 = 0.f, bv1 = 0.f;
        if (bias) { bv0 = bias[col]; bv1 = bias[col + 1]; }
#pragma unroll
        for (int mt = 0; mt < 4; mt++) {
            const int row = bm + m0w + mt * 16 + group;
            float2 v0 = make_float2(c[mt][nt][0] + bv0, c[mt][nt][1] + bv1);
            float2 v1 = make_float2(c[mt][nt][2] + bv0, c[mt][nt][3] + bv1);
            *(float2*)&C[(size_t)row * N + col]       = v0;
            *(float2*)&C[(size_t)(row + 8) * N + col] = v1;
        }
    }
}

// ---------------------------------------------------------------------------
// x -> tf32 round + k-permute. Processes 8 floats (one k-group) per thread.
// storage [0..7] = logical [0,4,1,5,2,6,3,7]
// ---------------------------------------------------------------------------
__global__ void tf32_round_kernel(const float* __restrict__ in,
                                  float* __restrict__ out, int n8)
{
    int i = blockIdx.x * 256 + threadIdx.x;
    if (i < n8) {
        float4 a = ((const float4*)in)[2 * i];       // logical k 0..3
        float4 b = ((const float4*)in)[2 * i + 1];   // logical k 4..7
        float4 o0, o1;
        o0.x = rnd(a.x); o0.y = rnd(b.x); o0.z = rnd(a.y); o0.w = rnd(b.y);
        o1.x = rnd(a.z); o1.y = rnd(b.z); o1.z = rnd(a.w); o1.w = rnd(b.w);
        ((float4*)out)[2 * i]     = o0;
        ((float4*)out)[2 * i + 1] = o1;
    }
}

// ---------------------------------------------------------------------------
// Weight transpose + tf32 round + k-permute: WT[n][sigma(k)] = rna(W[k][n])
// ---------------------------------------------------------------------------
__global__ void transpose_kernel(const float* __restrict__ W,
                                 float* __restrict__ WT, int R, int Cc)
{
    __shared__ float t[32][33];
    int x = blockIdx.x * 32 + threadIdx.x;
    int y = blockIdx.y * 32 + threadIdx.y;
    if (x < Cc && y < R) t[threadIdx.y][threadIdx.x] = W[y * Cc + x];
    __syncthreads();
    x = blockIdx.y * 32 + threadIdx.x;   // k index
    y = blockIdx.x * 32 + threadIdx.y;   // n index
    if (x < R && y < Cc) {
        int xs = (x & ~7) | (((x & 3) << 1) | ((x >> 2) & 1));
        WT[y * R + xs] = rnd(t[threadIdx.x][threadIdx.y]);
    }
}

__global__ void bias_kernel(const float* __restrict__ pos_emb,
                            float* __restrict__ biasG)
{
    int e = blockIdx.x * 256 + threadIdx.x;
    if (e < NT * NT) {
        int i = e / NT, j = e - i * NT;
        int dx = j / WS - i / WS + (WS - 1);
        int dy = j % WS - i % WS + (WS - 1);
        biasG[e] = pos_emb[dx * (2 * WS - 1) + dy];
    }
}

// ---------------------------------------------------------------------------
// Window attention v4 (flash-style mma, unchanged math). Epilogue stores
// k-permuted columns for GEMM2's LDS.64 path.
// ---------------------------------------------------------------------------
#define AST 36

__global__ __launch_bounds__(128) void attn_kernel(
    const float* __restrict__ qkv,
    const float* __restrict__ biasG,
    float* __restrict__ out)
{
    __shared__ float qs[64 * AST];
    __shared__ float ks[56 * AST];
    __shared__ float vs[56 * AST];
    __shared__ int   rowbase[NT];

    const int tid = threadIdx.x;
    const int wm  = tid >> 5;
    const int lane = tid & 31;
    const int group = lane >> 2;
    const int tig   = lane & 3;
    const int w = blockIdx.x;
    const int h = blockIdx.y;
    const int b = blockIdx.z;
    const int wr = w >> 3, wc = w & 7;

    if (tid < NT) {
        int ty = tid / WS, tx = tid - ty * WS;
        rowbase[tid] = (b * 56 + wr * WS + ty) * 56 + wc * WS + tx;
    }
    for (int i = tid; i < 15 * 32; i += 128) {
        int r = 49 + i / 32, cidx = i & 31;
        qs[r * AST + cidx] = 0.f;
    }
    for (int i = tid; i < 7 * 32; i += 128) {
        int r = 49 + i / 32, cidx = i & 31;
        ks[r * AST + cidx] = 0.f;
        vs[r * AST + cidx] = 0.f;
    }
    __syncthreads();

    for (int f = tid; f < NT * 8; f += 128) {
        int t = f >> 3, d4 = (f & 7) * 4;
        size_t base = (size_t)rowbase[t] * QKV_N + h * HD + d4;
        float4 qq = *(const float4*)&qkv[base];
        float4 kk = *(const float4*)&qkv[base + 256];
        float4 vv = *(const float4*)&qkv[base + 512];
        float* qp = &qs[t * AST + d4];
        float* kp = &ks[t * AST + d4];
        float* vp = &vs[t * AST + d4];
        qp[0] = rnd(qq.x); qp[1] = rnd(qq.y); qp[2] = rnd(qq.z); qp[3] = rnd(qq.w);
        kp[0] = rnd(kk.x); kp[1] = rnd(kk.y); kp[2] = rnd(kk.z); kp[3] = rnd(kk.w);
        vp[0] = rnd(vv.x); vp[1] = rnd(vv.y); vp[2] = rnd(vv.z); vp[3] = rnd(vv.w);
    }
    __syncthreads();

    const uint32_t* qb = (const uint32_t*)qs;
    const uint32_t* kb = (const uint32_t*)ks;
    const uint32_t* vb = (const uint32_t*)vs;
    const int row_lo = 16 * wm + group;
    const int row_hi = row_lo + 8;

    float sfrag[7][4];
#pragma unroll
    for (int jt = 0; jt < 7; jt++)
#pragma unroll
        for (int r = 0; r < 4; r++) sfrag[jt][r] = 0.f;

#pragma unroll
    for (int kk = 0; kk < 4; kk++) {
        const int kc = 8 * kk + tig;
        uint32_t a0 = qb[row_lo * AST + kc];
        uint32_t a1 = qb[row_hi * AST + kc];
        uint32_t a2 = qb[row_lo * AST + kc + 4];
        uint32_t a3 = qb[row_hi * AST + kc + 4];
#pragma unroll
        for (int jt = 0; jt < 7; jt++) {
            const int j = 8 * jt + group;
            uint32_t b0 = kb[j * AST + kc];
            uint32_t b1 = kb[j * AST + kc + 4];
            mma_tf32(sfrag[jt], a0, a1, a2, a3, b0, b1);
        }
    }

    float m_lo = -1e30f, m_hi = -1e30f;
#pragma unroll
    for (int jt = 0; jt < 7; jt++) {
        const int col0 = 8 * jt + 2 * tig;
#pragma unroll
        for (int r = 0; r < 4; r++) {
            const int col = col0 + (r & 1);
            const int row = (r < 2) ? row_lo : row_hi;
            float val;
            if (row < NT && col < NT)
                val = sfrag[jt][r] * SCALE + __ldg(&biasG[row * NT + col]);
            else
                val = -1e30f;
            sfrag[jt][r] = val;
            if (r < 2) m_lo = fmaxf(m_lo, val); else m_hi = fmaxf(m_hi, val);
        }
    }
    m_lo = fmaxf(m_lo, __shfl_xor_sync(0xffffffffu, m_lo, 1));
    m_lo = fmaxf(m_lo, __shfl_xor_sync(0xffffffffu, m_lo, 2));
    m_hi = fmaxf(m_hi, __shfl_xor_sync(0xffffffffu, m_hi, 1));
    m_hi = fmaxf(m_hi, __shfl_xor_sync(0xffffffffu, m_hi, 2));

    float s_lo = 0.f, s_hi = 0.f;
#pragma unroll
    for (int jt = 0; jt < 7; jt++) {
#pragma unroll
        for (int r = 0; r < 4; r++) {
            float e = __expf(sfrag[jt][r] - ((r < 2) ? m_lo : m_hi));
            sfrag[jt][r] = e;
            if (r < 2) s_lo += e; else s_hi += e;
        }
    }
    s_lo += __shfl_xor_sync(0xffffffffu, s_lo, 1);
    s_lo += __shfl_xor_sync(0xffffffffu, s_lo, 2);
    s_hi += __shfl_xor_sync(0xffffffffu, s_hi, 1);
    s_hi += __shfl_xor_sync(0xffffffffu, s_hi, 2);

    float o[4][4];
#pragma unroll
    for (int nt = 0; nt < 4; nt++)
#pragma unroll
        for (int r = 0; r < 4; r++) o[nt][r] = 0.f;

    const int srcA = (lane & ~3) | (tig >> 1);
    const int srcB = srcA + 2;
    const bool odd = (tig & 1);

#pragma unroll
    for (int kt = 0; kt < 7; kt++) {
        float x0 = sfrag[kt][0], x1 = sfrag[kt][1];
        float x2 = sfrag[kt][2], x3 = sfrag[kt][3];
        float y0  = __shfl_sync(0xffffffffu, x0, srcA);
        float y1  = __shfl_sync(0xffffffffu, x1, srcA);
        float y0b = __shfl_sync(0xffffffffu, x0, srcB);
        float y1b = __shfl_sync(0xffffffffu, x1, srcB);
        float z0  = __shfl_sync(0xffffffffu, x2, srcA);
        float z1  = __shfl_sync(0xffffffffu, x3, srcA);
        float z0b = __shfl_sync(0xffffffffu, x2, srcB);
        float z1b = __shfl_sync(0xffffffffu, x3, srcB);
        uint32_t a0 = f2tf32(odd ? y1  : y0);
        uint32_t a1 = f2tf32(odd ? z1  : z0);
        uint32_t a2 = f2tf32(odd ? y1b : y0b);
        uint32_t a3 = f2tf32(odd ? z1b : z0b);

        const int j0 = 8 * kt + tig;
#pragma unroll
        for (int nt = 0; nt < 4; nt++) {
            const int d0 = 8 * nt + group;
            uint32_t b0 = vb[j0 * AST + d0];
            uint32_t b1 = vb[(j0 + 4) * AST + d0];
            mma_tf32(o[nt], a0, a1, a2, a3, b0, b1);
        }
    }

    // store: logical cols (2t, 2t+1) -> permuted positions (p, p+2),
    // p = ((t&1)<<2) | (t>>1). tf32-rounded for GEMM2.
    const float inv_lo = 1.f / s_lo;
    const float inv_hi = 1.f / s_hi;
    const int p = ((tig & 1) << 2) | (tig >> 1);
    if (row_lo < NT) {
        float* orow = &out[(size_t)rowbase[row_lo] * DIM + h * HD];
#pragma unroll
        for (int nt = 0; nt < 4; nt++) {
            orow[8 * nt + p]     = rnd(o[nt][0] * inv_lo);
            orow[8 * nt + p + 2] = rnd(o[nt][1] * inv_lo);
        }
    }
    if (row_hi < NT) {
        float* orow = &out[(size_t)rowbase[row_hi] * DIM + h * HD];
#pragma unroll
        for (int nt = 0; nt < 4; nt++) {
            orow[8 * nt + p]     = rnd(o[nt][2] * inv_hi);
            orow[8 * nt + p + 2] = rnd(o[nt][3] * inv_hi);
        }
    }
}

// ---------------------------------------------------------------------------
extern "C" void kernel_launch(void* const* d_in, const int* in_sizes, int n_in,
                              void* d_out, int out_size)
{
    const float* x      = (const float*)d_in[0];
    const float* w_qkv  = (const float*)d_in[1];
    const float* w_out  = (const float*)d_in[2];
    const float* b_out  = (const float*)d_in[3];
    const float* pos    = (const float*)d_in[4];
    float* out = (float*)d_out;

    float *qkv_ptr, *attn_ptr, *xtf_ptr, *bias_ptr, *wqkvT_ptr, *woutT_ptr;
    cudaGetSymbolAddress((void**)&qkv_ptr,  g_qkv);
    cudaGetSymbolAddress((void**)&attn_ptr, g_attn);
    cudaGetSymbolAddress((void**)&xtf_ptr,  g_xtf);
    cudaGetSymbolAddress((void**)&bias_ptr, g_bias);
    cudaGetSymbolAddress((void**)&wqkvT_ptr, g_wqkvT);
    cudaGetSymbolAddress((void**)&woutT_ptr, g_woutT);

    const int SMEM_BYTES = 4 * TILEF * (int)sizeof(float);   // 81920
    static bool attr_set = false;
    if (!attr_set) {
        cudaFuncSetAttribute(mma_gemm,
            cudaFuncAttributeMaxDynamicSharedMemorySize, SMEM_BYTES);
        attr_set = true;
    }

    // 0) prep
    bias_kernel<<<(NT * NT + 255) / 256, 256>>>(pos, bias_ptr);
    {
        dim3 blk(32, 32);
        transpose_kernel<<<dim3(QKV_N / 32, DIM / 32), blk>>>(w_qkv, wqkvT_ptr, DIM, QKV_N);
        transpose_kernel<<<dim3(DIM / 32, DIM / 32), blk>>>(w_out, woutT_ptr, DIM, DIM);
    }
    {
        int n8 = M_TOK * DIM / 8;
        tf32_round_kernel<<<(n8 + 255) / 256, 256>>>(x, xtf_ptr, n8);
    }

    // 1) qkv = x @ w_qkv
    {
        dim3 grid(QKV_N / 128, M_TOK / 128);
        mma_gemm<<<grid, 256, SMEM_BYTES>>>(xtf_ptr, wqkvT_ptr, qkv_ptr, nullptr, QKV_N, DIM);
    }
    // 2) window attention
    {
        dim3 grid(64, HEADS, 32);
        attn_kernel<<<grid, 128>>>(qkv_ptr, bias_ptr, attn_ptr);
    }
    // 3) out = attn @ w_out + b_out
    {
        dim3 grid(DIM / 128, M_TOK / 128);
        mma_gemm<<<grid, 256, SMEM_BYTES>>>(attn_ptr, woutT_ptr, out, b_out, DIM, DIM);
    }
}

// round 11
// speedup vs baseline: 1.3237x; 1.3237x over previous
#include <cuda_runtime.h>
#include <cuda_fp16.h>
#include <cstdint>

#define M_TOK   100352      // 32 * 56 * 56
#define DIM     256
#define QKV_N   768
#define HEADS   8
#define HD      32
#define WS      7
#define NT      49
#define SCALE   0.17677669529663687f

// Scratch (device globals: allocation-free per harness rules)
__device__ __half g_qkv[(size_t)M_TOK * QKV_N];   // 154 MB fp16
__device__ __half g_attn[(size_t)M_TOK * DIM];    // 51 MB fp16
__device__ __half g_x16[(size_t)M_TOK * DIM];     // 51 MB fp16 x
__device__ float  g_bias[NT * NT];
__device__ __half g_wqkvT[QKV_N * DIM];           // transposed fp16
__device__ __half g_woutT[DIM * DIM];             // transposed fp16

__device__ __forceinline__ uint32_t f2tf32(float f) {
    uint32_t r;
    asm("cvt.rna.tf32.f32 %0, %1;" : "=r"(r) : "f"(f));
    return r;
}
__device__ __forceinline__ uint32_t smem_u32(const void* p) {
    uint32_t a;
    asm("{ .reg .u64 t; cvta.to.shared.u64 t, %1; cvt.u32.u64 %0, t; }"
        : "=r"(a) : "l"(p));
    return a;
}
__device__ __forceinline__ void cpasync16(uint32_t dst, const void* src) {
    asm volatile("cp.async.ca.shared.global [%0], [%1], 16;"
                 :: "r"(dst), "l"(src));
}
__device__ __forceinline__ void mma_tf32(float* c, uint32_t a0, uint32_t a1,
                                         uint32_t a2, uint32_t a3,
                                         uint32_t b0, uint32_t b1) {
    asm volatile(
        "mma.sync.aligned.m16n8k8.row.col.f32.tf32.tf32.f32 "
        "{%0,%1,%2,%3}, {%4,%5,%6,%7}, {%8,%9}, {%0,%1,%2,%3};"
        : "+f"(c[0]), "+f"(c[1]), "+f"(c[2]), "+f"(c[3])
        : "r"(a0), "r"(a1), "r"(a2), "r"(a3), "r"(b0), "r"(b1));
}
__device__ __forceinline__ void mma_f16(float* c, uint32_t a0, uint32_t a1,
                                        uint32_t a2, uint32_t a3,
                                        uint32_t b0, uint32_t b1) {
    asm volatile(
        "mma.sync.aligned.m16n8k16.row.col.f32.f16.f16.f32 "
        "{%0,%1,%2,%3}, {%4,%5,%6,%7}, {%8,%9}, {%0,%1,%2,%3};"
        : "+f"(c[0]), "+f"(c[1]), "+f"(c[2]), "+f"(c[3])
        : "r"(a0), "r"(a1), "r"(a2), "r"(a3), "r"(b0), "r"(b1));
}
__device__ __forceinline__ void ldsm_x4(uint32_t& r0, uint32_t& r1,
                                        uint32_t& r2, uint32_t& r3, uint32_t addr) {
    asm volatile("ldmatrix.sync.aligned.m8n8.x4.shared.b16 {%0,%1,%2,%3}, [%4];"
                 : "=r"(r0), "=r"(r1), "=r"(r2), "=r"(r3) : "r"(addr));
}

// ---------------------------------------------------------------------------
// fp16 m16n8k16 GEMM, ldmatrix fragments, 3-stage cp.async pipeline.
// C[M,N] = A[M,K] @ BT[N,K]^T (+bias). 128x128 tile, 8 warps (2x4 of 64x32).
// Smem pitch 40 halves (80B): every LDSM phase tiles all 32 banks.
// ---------------------------------------------------------------------------
#define PH     40            // pitch in halves
#define PHB    80            // pitch bytes
#define ATILEB (128 * PHB)   // 10240 B per operand tile
#define STAGEB (2 * ATILEB)  // 20480 B per stage
#define NSTAGE 3

template<bool HALF_OUT>
__global__ __launch_bounds__(256, 2) void hgemm(
    const __half* __restrict__ A, const __half* __restrict__ BT,
    void* __restrict__ Cv, const float* __restrict__ bias, int N, int K)
{
    extern __shared__ __half smh[];
    const uint32_t smbase = smem_u32(smh);

    const int tid  = threadIdx.x;
    const int wid  = tid >> 5;
    const int lane = tid & 31;
    const int group = lane >> 2;
    const int tig   = lane & 3;
    const int m0w = (wid & 1) * 64;
    const int n0w = (wid >> 1) * 32;
    const int bm = blockIdx.y * 128;
    const int bn = blockIdx.x * 128;

    // loaders: 128 rows x 4 segs of 16B per operand; thread does 2 rows each
    const int lrow = tid >> 2;           // 0..63
    const int lseg = tid & 3;

    float c[4][4][4];
#pragma unroll
    for (int mt = 0; mt < 4; mt++)
#pragma unroll
        for (int nt = 0; nt < 4; nt++)
#pragma unroll
            for (int r = 0; r < 4; r++) c[mt][nt][r] = 0.f;

    const int nch = K >> 5;

    auto issue = [&](int cc, int st) {
        const int k0 = cc * 32;
        const uint32_t sb = smbase + (uint32_t)st * STAGEB;
#pragma unroll
        for (int i = 0; i < 2; i++) {
            const int row = lrow + 64 * i;
            cpasync16(sb + (uint32_t)(row * PHB + lseg * 16),
                      &A[(size_t)(bm + row) * K + k0 + lseg * 8]);
            cpasync16(sb + (uint32_t)(ATILEB + row * PHB + lseg * 16),
                      &BT[(size_t)(bn + row) * K + k0 + lseg * 8]);
        }
    };

    issue(0, 0);
    asm volatile("cp.async.commit_group;");
    if (nch > 1) issue(1, 1);
    asm volatile("cp.async.commit_group;");

    // ldmatrix lane-address components
    const int arow = m0w + (lane & 15);               // + mt*16
    const uint32_t acol = ((uint32_t)(lane >> 4)) * 16;   // 8 halves * 2B
    const int browb = n0w + 8 * (lane >> 4) + (lane & 7); // + 16*ntp
    const uint32_t bcol = ((uint32_t)((lane >> 3) & 1)) * 16;

    for (int cidx = 0; cidx < nch; cidx++) {
        const int st = cidx % NSTAGE;
        asm volatile("cp.async.wait_group 1;");
        __syncthreads();

        const uint32_t sb = smbase + (uint32_t)st * STAGEB;
#pragma unroll
        for (int k16 = 0; k16 < 2; k16++) {
            const uint32_t koff = (uint32_t)k16 * 32;
            uint32_t a[4][4], b[4][2];
#pragma unroll
            for (int mt = 0; mt < 4; mt++) {
                uint32_t addr = sb + (uint32_t)((arow + mt * 16) * PHB) + acol + koff;
                ldsm_x4(a[mt][0], a[mt][1], a[mt][2], a[mt][3], addr);
            }
#pragma unroll
            for (int ntp = 0; ntp < 2; ntp++) {
                uint32_t addr = sb + ATILEB
                              + (uint32_t)((browb + 16 * ntp) * PHB) + bcol + koff;
                ldsm_x4(b[2 * ntp][0], b[2 * ntp][1],
                        b[2 * ntp + 1][0], b[2 * ntp + 1][1], addr);
            }
#pragma unroll
            for (int mt = 0; mt < 4; mt++)
#pragma unroll
                for (int nt = 0; nt < 4; nt++)
                    mma_f16(c[mt][nt], a[mt][0], a[mt][1], a[mt][2], a[mt][3],
                            b[nt][0], b[nt][1]);
        }
        __syncthreads();
        if (cidx + 2 < nch) {
            issue(cidx + 2, (cidx + 2) % NSTAGE);
        }
        asm volatile("cp.async.commit_group;");
    }

    // Epilogue
#pragma unroll
    for (int nt = 0; nt < 4; nt++) {
        const int col = bn + n0w + nt * 8 + tig * 2;
        float bv0 = 0.f, bv1 = 0.f;
        if (!HALF_OUT && bias) { bv0 = bias[col]; bv1 = bias[col + 1]; }
#pragma unroll
        for (int mt = 0; mt < 4; mt++) {
            const int row = bm + m0w + mt * 16 + group;
            if (HALF_OUT) {
                __half* Ch = (__half*)Cv;
                *(__half2*)&Ch[(size_t)row * N + col] =
                    __floats2half2_rn(c[mt][nt][0], c[mt][nt][1]);
                *(__half2*)&Ch[(size_t)(row + 8) * N + col] =
                    __floats2half2_rn(c[mt][nt][2], c[mt][nt][3]);
            } else {
                float* Cf = (float*)Cv;
                *(float2*)&Cf[(size_t)row * N + col] =
                    make_float2(c[mt][nt][0] + bv0, c[mt][nt][1] + bv1);
                *(float2*)&Cf[(size_t)(row + 8) * N + col] =
                    make_float2(c[mt][nt][2] + bv0, c[mt][nt][3] + bv1);
            }
        }
    }
}

// ---------------------------------------------------------------------------
// x (fp32) -> fp16
// ---------------------------------------------------------------------------
__global__ void f2h_kernel(const float* __restrict__ in,
                           __half* __restrict__ out, int n4)
{
    int i = blockIdx.x * 256 + threadIdx.x;
    if (i < n4) {
        float4 v = ((const float4*)in)[i];
        __half2 h0 = __floats2half2_rn(v.x, v.y);
        __half2 h1 = __floats2half2_rn(v.z, v.w);
        ((__half2*)out)[2 * i]     = h0;
        ((__half2*)out)[2 * i + 1] = h1;
    }
}

// ---------------------------------------------------------------------------
// Weight transpose fp32 -> fp16: WT[n][k] = h(W[k][n])
// ---------------------------------------------------------------------------
__global__ void transpose_kernel(const float* __restrict__ W,
                                 __half* __restrict__ WT, int R, int Cc)
{
    __shared__ float t[32][33];
    int x = blockIdx.x * 32 + threadIdx.x;
    int y = blockIdx.y * 32 + threadIdx.y;
    if (x < Cc && y < R) t[threadIdx.y][threadIdx.x] = W[y * Cc + x];
    __syncthreads();
    x = blockIdx.y * 32 + threadIdx.x;   // k
    y = blockIdx.x * 32 + threadIdx.y;   // n
    if (x < R && y < Cc)
        WT[y * R + x] = __float2half_rn(t[threadIdx.x][threadIdx.y]);
}

__global__ void bias_kernel(const float* __restrict__ pos_emb,
                            float* __restrict__ biasG)
{
    int e = blockIdx.x * 256 + threadIdx.x;
    if (e < NT * NT) {
        int i = e / NT, j = e - i * NT;
        int dx = j / WS - i / WS + (WS - 1);
        int dy = j % WS - i % WS + (WS - 1);
        biasG[e] = pos_emb[dx * (2 * WS - 1) + dy];
    }
}

// ---------------------------------------------------------------------------
// Window attention (flash-style tf32 mma, R8 layout). Reads fp16 qkv
// (fp16->fp32 exact), writes fp16 attn-out for GEMM2.
// ---------------------------------------------------------------------------
#define AST 36

__global__ __launch_bounds__(128) void attn_kernel(
    const __half* __restrict__ qkv,
    const float* __restrict__ biasG,
    __half* __restrict__ out)
{
    __shared__ float qs[64 * AST];
    __shared__ float ks[56 * AST];
    __shared__ float vs[56 * AST];
    __shared__ int   rowbase[NT];

    const int tid = threadIdx.x;
    const int wm  = tid >> 5;
    const int lane = tid & 31;
    const int group = lane >> 2;
    const int tig   = lane & 3;
    const int w = blockIdx.x;
    const int h = blockIdx.y;
    const int b = blockIdx.z;
    const int wr = w >> 3, wc = w & 7;

    if (tid < NT) {
        int ty = tid / WS, tx = tid - ty * WS;
        rowbase[tid] = (b * 56 + wr * WS + ty) * 56 + wc * WS + tx;
    }
    for (int i = tid; i < 15 * 32; i += 128) {
        int r = 49 + i / 32, cidx = i & 31;
        qs[r * AST + cidx] = 0.f;
    }
    for (int i = tid; i < 7 * 32; i += 128) {
        int r = 49 + i / 32, cidx = i & 31;
        ks[r * AST + cidx] = 0.f;
        vs[r * AST + cidx] = 0.f;
    }
    __syncthreads();

    // Gather q/k/v: 8 halves (16B) per op; fp16->fp32 exact
    for (int f = tid; f < NT * 4; f += 128) {
        int t = f >> 2, d8 = (f & 3) * 8;
        size_t base = (size_t)rowbase[t] * QKV_N + h * HD + d8;
        const __half2* qh = (const __half2*)&qkv[base];
        const __half2* kh = (const __half2*)&qkv[base + 256];
        const __half2* vh = (const __half2*)&qkv[base + 512];
        float* qp = &qs[t * AST + d8];
        float* kp = &ks[t * AST + d8];
        float* vp = &vs[t * AST + d8];
#pragma unroll
        for (int j = 0; j < 4; j++) {
            float2 fq = __half22float2(qh[j]);
            float2 fk = __half22float2(kh[j]);
            float2 fv = __half22float2(vh[j]);
            qp[2 * j] = fq.x; qp[2 * j + 1] = fq.y;
            kp[2 * j] = fk.x; kp[2 * j + 1] = fk.y;
            vp[2 * j] = fv.x; vp[2 * j + 1] = fv.y;
        }
    }
    __syncthreads();

    const uint32_t* qb = (const uint32_t*)qs;
    const uint32_t* kb = (const uint32_t*)ks;
    const uint32_t* vb = (const uint32_t*)vs;
    const int row_lo = 16 * wm + group;
    const int row_hi = row_lo + 8;

    float sfrag[7][4];
#pragma unroll
    for (int jt = 0; jt < 7; jt++)
#pragma unroll
        for (int r = 0; r < 4; r++) sfrag[jt][r] = 0.f;

#pragma unroll
    for (int kk = 0; kk < 4; kk++) {
        const int kc = 8 * kk + tig;
        uint32_t a0 = qb[row_lo * AST + kc];
        uint32_t a1 = qb[row_hi * AST + kc];
        uint32_t a2 = qb[row_lo * AST + kc + 4];
        uint32_t a3 = qb[row_hi * AST + kc + 4];
#pragma unroll
        for (int jt = 0; jt < 7; jt++) {
            const int j = 8 * jt + group;
            uint32_t b0 = kb[j * AST + kc];
            uint32_t b1 = kb[j * AST + kc + 4];
            mma_tf32(sfrag[jt], a0, a1, a2, a3, b0, b1);
        }
    }

    float m_lo = -1e30f, m_hi = -1e30f;
#pragma unroll
    for (int jt = 0; jt < 7; jt++) {
        const int col0 = 8 * jt + 2 * tig;
#pragma unroll
        for (int r = 0; r < 4; r++) {
            const int col = col0 + (r & 1);
            const int row = (r < 2) ? row_lo : row_hi;
            float val;
            if (row < NT && col < NT)
                val = sfrag[jt][r] * SCALE + __ldg(&biasG[row * NT + col]);
            else
                val = -1e30f;
            sfrag[jt][r] = val;
            if (r < 2) m_lo = fmaxf(m_lo, val); else m_hi = fmaxf(m_hi, val);
        }
    }
    m_lo = fmaxf(m_lo, __shfl_xor_sync(0xffffffffu, m_lo, 1));
    m_lo = fmaxf(m_lo, __shfl_xor_sync(0xffffffffu, m_lo, 2));
    m_hi = fmaxf(m_hi, __shfl_xor_sync(0xffffffffu, m_hi, 1));
    m_hi = fmaxf(m_hi, __shfl_xor_sync(0xffffffffu, m_hi, 2));

    float s_lo = 0.f, s_hi = 0.f;
#pragma unroll
    for (int jt = 0; jt < 7; jt++) {
#pragma unroll
        for (int r = 0; r < 4; r++) {
            float e = __expf(sfrag[jt][r] - ((r < 2) ? m_lo : m_hi));
            sfrag[jt][r] = e;
            if (r < 2) s_lo += e; else s_hi += e;
        }
    }
    s_lo += __shfl_xor_sync(0xffffffffu, s_lo, 1);
    s_lo += __shfl_xor_sync(0xffffffffu, s_lo, 2);
    s_hi += __shfl_xor_sync(0xffffffffu, s_hi, 1);
    s_hi += __shfl_xor_sync(0xffffffffu, s_hi, 2);

    float o[4][4];
#pragma unroll
    for (int nt = 0; nt < 4; nt++)
#pragma unroll
        for (int r = 0; r < 4; r++) o[nt][r] = 0.f;

    const int srcA = (lane & ~3) | (tig >> 1);
    const int srcB = srcA + 2;
    const bool odd = (tig & 1);

#pragma unroll
    for (int kt = 0; kt < 7; kt++) {
        float x0 = sfrag[kt][0], x1 = sfrag[kt][1];
        float x2 = sfrag[kt][2], x3 = sfrag[kt][3];
        float y0  = __shfl_sync(0xffffffffu, x0, srcA);
        float y1  = __shfl_sync(0xffffffffu, x1, srcA);
        float y0b = __shfl_sync(0xffffffffu, x0, srcB);
        float y1b = __shfl_sync(0xffffffffu, x1, srcB);
        float z0  = __shfl_sync(0xffffffffu, x2, srcA);
        float z1  = __shfl_sync(0xffffffffu, x3, srcA);
        float z0b = __shfl_sync(0xffffffffu, x2, srcB);
        float z1b = __shfl_sync(0xffffffffu, x3, srcB);
        uint32_t a0 = f2tf32(odd ? y1  : y0);
        uint32_t a1 = f2tf32(odd ? z1  : z0);
        uint32_t a2 = f2tf32(odd ? y1b : y0b);
        uint32_t a3 = f2tf32(odd ? z1b : z0b);

        const int j0 = 8 * kt + tig;
#pragma unroll
        for (int nt = 0; nt < 4; nt++) {
            const int d0 = 8 * nt + group;
            uint32_t b0 = vb[j0 * AST + d0];
            uint32_t b1 = vb[(j0 + 4) * AST + d0];
            mma_tf32(o[nt], a0, a1, a2, a3, b0, b1);
        }
    }

    const float inv_lo = 1.f / s_lo;
    const float inv_hi = 1.f / s_hi;
    if (row_lo < NT) {
        __half* orow = &out[(size_t)rowbase[row_lo] * DIM + h * HD];
#pragma unroll
        for (int nt = 0; nt < 4; nt++)
            *(__half2*)&orow[8 * nt + 2 * tig] =
                __floats2half2_rn(o[nt][0] * inv_lo, o[nt][1] * inv_lo);
    }
    if (row_hi < NT) {
        __half* orow = &out[(size_t)rowbase[row_hi] * DIM + h * HD];
#pragma unroll
        for (int nt = 0; nt < 4; nt++)
            *(__half2*)&orow[8 * nt + 2 * tig] =
                __floats2half2_rn(o[nt][2] * inv_hi, o[nt][3] * inv_hi);
    }
}

// ---------------------------------------------------------------------------
extern "C" void kernel_launch(void* const* d_in, const int* in_sizes, int n_in,
                              void* d_out, int out_size)
{
    const float* x      = (const float*)d_in[0];
    const float* w_qkv  = (const float*)d_in[1];
    const float* w_out  = (const float*)d_in[2];
    const float* b_out  = (const float*)d_in[3];
    const float* pos    = (const float*)d_in[4];
    float* out = (float*)d_out;

    __half *qkv_ptr, *attn_ptr, *x16_ptr, *wqkvT_ptr, *woutT_ptr;
    float *bias_ptr;
    cudaGetSymbolAddress((void**)&qkv_ptr,  g_qkv);
    cudaGetSymbolAddress((void**)&attn_ptr, g_attn);
    cudaGetSymbolAddress((void**)&x16_ptr,  g_x16);
    cudaGetSymbolAddress((void**)&bias_ptr, g_bias);
    cudaGetSymbolAddress((void**)&wqkvT_ptr, g_wqkvT);
    cudaGetSymbolAddress((void**)&woutT_ptr, g_woutT);

    const int SMEM_BYTES = NSTAGE * STAGEB;   // 61440
    static bool attr_set = false;
    if (!attr_set) {
        cudaFuncSetAttribute(hgemm<true>,
            cudaFuncAttributeMaxDynamicSharedMemorySize, SMEM_BYTES);
        cudaFuncSetAttribute(hgemm<false>,
            cudaFuncAttributeMaxDynamicSharedMemorySize, SMEM_BYTES);
        attr_set = true;
    }

    // 0) prep
    bias_kernel<<<(NT * NT + 255) / 256, 256>>>(pos, bias_ptr);
    {
        dim3 blk(32, 32);
        transpose_kernel<<<dim3(QKV_N / 32, DIM / 32), blk>>>(w_qkv, wqkvT_ptr, DIM, QKV_N);
        transpose_kernel<<<dim3(DIM / 32, DIM / 32), blk>>>(w_out, woutT_ptr, DIM, DIM);
    }
    {
        int n4 = M_TOK * DIM / 4;
        f2h_kernel<<<(n4 + 255) / 256, 256>>>(x, x16_ptr, n4);
    }

    // 1) qkv = x @ w_qkv   (fp16 mma, fp16 out)
    {
        dim3 grid(QKV_N / 128, M_TOK / 128);
        hgemm<true><<<grid, 256, SMEM_BYTES>>>(x16_ptr, wqkvT_ptr, qkv_ptr, nullptr, QKV_N, DIM);
    }
    // 2) window attention
    {
        dim3 grid(64, HEADS, 32);
        attn_kernel<<<grid, 128>>>(qkv_ptr, bias_ptr, attn_ptr);
    }
    // 3) out = attn @ w_out + b_out   (fp16 mma, fp32 out + bias)
    {
        dim3 grid(DIM / 128, M_TOK / 128);
        hgemm<false><<<grid, 256, SMEM_BYTES>>>(attn_ptr, woutT_ptr, out, b_out, DIM, DIM);
    }
}

// round 12
// speedup vs baseline: 1.5264x; 1.1531x over previous
#include <cuda_runtime.h>
#include <cuda_fp16.h>
#include <cstdint>

#define M_TOK   100352      // 32 * 56 * 56
#define DIM     256
#define QKV_N   768
#define HEADS   8
#define HD      32
#define WS      7
#define NT      49
#define SCALE   0.17677669529663687f

// Scratch (device globals: allocation-free per harness rules)
__device__ __half g_qkv[(size_t)M_TOK * QKV_N];   // 154 MB fp16
__device__ __half g_attn[(size_t)M_TOK * DIM];    // 51 MB fp16
__device__ __half g_x16[(size_t)M_TOK * DIM];     // 51 MB fp16 x
__device__ float  g_bias[NT * NT];
__device__ __half g_wqkvT[QKV_N * DIM];           // transposed fp16
__device__ __half g_woutT[DIM * DIM];             // transposed fp16

__device__ __forceinline__ uint32_t smem_u32(const void* p) {
    uint32_t a;
    asm("{ .reg .u64 t; cvta.to.shared.u64 t, %1; cvt.u32.u64 %0, t; }"
        : "=r"(a) : "l"(p));
    return a;
}
__device__ __forceinline__ void cpasync16(uint32_t dst, const void* src) {
    asm volatile("cp.async.ca.shared.global [%0], [%1], 16;"
                 :: "r"(dst), "l"(src));
}
__device__ __forceinline__ void mma_f16(float* c, uint32_t a0, uint32_t a1,
                                        uint32_t a2, uint32_t a3,
                                        uint32_t b0, uint32_t b1) {
    asm volatile(
        "mma.sync.aligned.m16n8k16.row.col.f32.f16.f16.f32 "
        "{%0,%1,%2,%3}, {%4,%5,%6,%7}, {%8,%9}, {%0,%1,%2,%3};"
        : "+f"(c[0]), "+f"(c[1]), "+f"(c[2]), "+f"(c[3])
        : "r"(a0), "r"(a1), "r"(a2), "r"(a3), "r"(b0), "r"(b1));
}
__device__ __forceinline__ void ldsm_x4(uint32_t& r0, uint32_t& r1,
                                        uint32_t& r2, uint32_t& r3, uint32_t addr) {
    asm volatile("ldmatrix.sync.aligned.m8n8.x4.shared.b16 {%0,%1,%2,%3}, [%4];"
                 : "=r"(r0), "=r"(r1), "=r"(r2), "=r"(r3) : "r"(addr));
}
__device__ __forceinline__ uint32_t pack_h2(float lo, float hi) {
    __half2 h = __floats2half2_rn(lo, hi);
    return *(uint32_t*)&h;
}

// ---------------------------------------------------------------------------
// fp16 m16n8k16 GEMM, ldmatrix fragments, 3-stage cp.async pipeline.
// (unchanged from R11 — passing at rel_err 6.0e-4)
// ---------------------------------------------------------------------------
#define PH     40            // pitch in halves
#define PHB    80            // pitch bytes
#define ATILEB (128 * PHB)
#define STAGEB (2 * ATILEB)
#define NSTAGE 3

template<bool HALF_OUT>
__global__ __launch_bounds__(256, 2) void hgemm(
    const __half* __restrict__ A, const __half* __restrict__ BT,
    void* __restrict__ Cv, const float* __restrict__ bias, int N, int K)
{
    extern __shared__ __half smh[];
    const uint32_t smbase = smem_u32(smh);

    const int tid  = threadIdx.x;
    const int wid  = tid >> 5;
    const int lane = tid & 31;
    const int group = lane >> 2;
    const int tig   = lane & 3;
    const int m0w = (wid & 1) * 64;
    const int n0w = (wid >> 1) * 32;
    const int bm = blockIdx.y * 128;
    const int bn = blockIdx.x * 128;

    const int lrow = tid >> 2;
    const int lseg = tid & 3;

    float c[4][4][4];
#pragma unroll
    for (int mt = 0; mt < 4; mt++)
#pragma unroll
        for (int nt = 0; nt < 4; nt++)
#pragma unroll
            for (int r = 0; r < 4; r++) c[mt][nt][r] = 0.f;

    const int nch = K >> 5;

    auto issue = [&](int cc, int st) {
        const int k0 = cc * 32;
        const uint32_t sb = smbase + (uint32_t)st * STAGEB;
#pragma unroll
        for (int i = 0; i < 2; i++) {
            const int row = lrow + 64 * i;
            cpasync16(sb + (uint32_t)(row * PHB + lseg * 16),
                      &A[(size_t)(bm + row) * K + k0 + lseg * 8]);
            cpasync16(sb + (uint32_t)(ATILEB + row * PHB + lseg * 16),
                      &BT[(size_t)(bn + row) * K + k0 + lseg * 8]);
        }
    };

    issue(0, 0);
    asm volatile("cp.async.commit_group;");
    if (nch > 1) issue(1, 1);
    asm volatile("cp.async.commit_group;");

    const int arow = m0w + (lane & 15);
    const uint32_t acol = ((uint32_t)(lane >> 4)) * 16;
    const int browb = n0w + 8 * (lane >> 4) + (lane & 7);
    const uint32_t bcol = ((uint32_t)((lane >> 3) & 1)) * 16;

    for (int cidx = 0; cidx < nch; cidx++) {
        const int st = cidx % NSTAGE;
        asm volatile("cp.async.wait_group 1;");
        __syncthreads();

        const uint32_t sb = smbase + (uint32_t)st * STAGEB;
#pragma unroll
        for (int k16 = 0; k16 < 2; k16++) {
            const uint32_t koff = (uint32_t)k16 * 32;
            uint32_t a[4][4], b[4][2];
#pragma unroll
            for (int mt = 0; mt < 4; mt++) {
                uint32_t addr = sb + (uint32_t)((arow + mt * 16) * PHB) + acol + koff;
                ldsm_x4(a[mt][0], a[mt][1], a[mt][2], a[mt][3], addr);
            }
#pragma unroll
            for (int ntp = 0; ntp < 2; ntp++) {
                uint32_t addr = sb + ATILEB
                              + (uint32_t)((browb + 16 * ntp) * PHB) + bcol + koff;
                ldsm_x4(b[2 * ntp][0], b[2 * ntp][1],
                        b[2 * ntp + 1][0], b[2 * ntp + 1][1], addr);
            }
#pragma unroll
            for (int mt = 0; mt < 4; mt++)
#pragma unroll
                for (int nt = 0; nt < 4; nt++)
                    mma_f16(c[mt][nt], a[mt][0], a[mt][1], a[mt][2], a[mt][3],
                            b[nt][0], b[nt][1]);
        }
        __syncthreads();
        if (cidx + 2 < nch) {
            issue(cidx + 2, (cidx + 2) % NSTAGE);
        }
        asm volatile("cp.async.commit_group;");
    }

#pragma unroll
    for (int nt = 0; nt < 4; nt++) {
        const int col = bn + n0w + nt * 8 + tig * 2;
        float bv0 = 0.f, bv1 = 0.f;
        if (!HALF_OUT && bias) { bv0 = bias[col]; bv1 = bias[col + 1]; }
#pragma unroll
        for (int mt = 0; mt < 4; mt++) {
            const int row = bm + m0w + mt * 16 + group;
            if (HALF_OUT) {
                __half* Ch = (__half*)Cv;
                *(__half2*)&Ch[(size_t)row * N + col] =
                    __floats2half2_rn(c[mt][nt][0], c[mt][nt][1]);
                *(__half2*)&Ch[(size_t)(row + 8) * N + col] =
                    __floats2half2_rn(c[mt][nt][2], c[mt][nt][3]);
            } else {
                float* Cf = (float*)Cv;
                *(float2*)&Cf[(size_t)row * N + col] =
                    make_float2(c[mt][nt][0] + bv0, c[mt][nt][1] + bv1);
                *(float2*)&Cf[(size_t)(row + 8) * N + col] =
                    make_float2(c[mt][nt][2] + bv0, c[mt][nt][3] + bv1);
            }
        }
    }
}

// ---------------------------------------------------------------------------
__global__ void f2h_kernel(const float* __restrict__ in,
                           __half* __restrict__ out, int n4)
{
    int i = blockIdx.x * 256 + threadIdx.x;
    if (i < n4) {
        float4 v = ((const float4*)in)[i];
        ((__half2*)out)[2 * i]     = __floats2half2_rn(v.x, v.y);
        ((__half2*)out)[2 * i + 1] = __floats2half2_rn(v.z, v.w);
    }
}

__global__ void transpose_kernel(const float* __restrict__ W,
                                 __half* __restrict__ WT, int R, int Cc)
{
    __shared__ float t[32][33];
    int x = blockIdx.x * 32 + threadIdx.x;
    int y = blockIdx.y * 32 + threadIdx.y;
    if (x < Cc && y < R) t[threadIdx.y][threadIdx.x] = W[y * Cc + x];
    __syncthreads();
    x = blockIdx.y * 32 + threadIdx.x;   // k
    y = blockIdx.x * 32 + threadIdx.y;   // n
    if (x < R && y < Cc)
        WT[y * R + x] = __float2half_rn(t[threadIdx.x][threadIdx.y]);
}

__global__ void bias_kernel(const float* __restrict__ pos_emb,
                            float* __restrict__ biasG)
{
    int e = blockIdx.x * 256 + threadIdx.x;
    if (e < NT * NT) {
        int i = e / NT, j = e - i * NT;
        int dx = j / WS - i / WS + (WS - 1);
        int dy = j % WS - i % WS + (WS - 1);
        biasG[e] = pos_emb[dx * (2 * WS - 1) + dy];
    }
}

// ---------------------------------------------------------------------------
// Window attention v5: full fp16 mma + ldmatrix.
// QK: A = Q rows (ldmatrix), B = K rows [j][d] (ldmatrix, GEMM-validated
// pattern). Softmax on C-frags. PV: P->A frags via pure half2 packing
// (C cols (2t,2t+1) == A half2 lanes, NO shuffles); B = V^T [d][j] built
// transposed in the gather.
// ---------------------------------------------------------------------------
#define QP  40    // q/k pitch (halves)
#define QPB 80
#define VP  72    // vsT pitch (halves)
#define VPB 144

__global__ __launch_bounds__(128) void attn_kernel(
    const __half* __restrict__ qkv,
    const float* __restrict__ biasG,
    __half* __restrict__ out)
{
    __shared__ __half qs[64 * QP];    // rows 49..63 zero
    __shared__ __half ks[64 * QP];    // rows 49..63 zero
    __shared__ __half vsT[32 * VP];   // [d][j], cols 49..63 zero
    __shared__ int    rowbase[NT];

    const int tid = threadIdx.x;
    const int wm  = tid >> 5;
    const int lane = tid & 31;
    const int group = lane >> 2;
    const int tig   = lane & 3;
    const int w = blockIdx.x;
    const int h = blockIdx.y;
    const int b = blockIdx.z;
    const int wr = w >> 3, wc = w & 7;

    if (tid < NT) {
        int ty = tid / WS, tx = tid - ty * WS;
        rowbase[tid] = (b * 56 + wr * WS + ty) * 56 + wc * WS + tx;
    }
    // zero pad: qs/ks rows 49..63 (data cols 0..31), vsT fully
    for (int i = tid; i < 15 * 32; i += 128) {
        int r = 49 + i / 32, c = i & 31;
        qs[r * QP + c] = __float2half(0.f);
        ks[r * QP + c] = __float2half(0.f);
    }
    for (int i = tid; i < 32 * VP / 2; i += 128)
        ((uint32_t*)vsT)[i] = 0u;
    __syncthreads();

    // Gather: q,k straight 16B copies; v transposed into vsT
    for (int f = tid; f < NT * 4; f += 128) {
        int t = f >> 2, seg = f & 3;
        size_t base = (size_t)rowbase[t] * QKV_N + h * HD + seg * 8;
        uint4 qv = *(const uint4*)&qkv[base];
        uint4 kv = *(const uint4*)&qkv[base + 256];
        uint4 vv = *(const uint4*)&qkv[base + 512];
        *(uint4*)&qs[t * QP + seg * 8] = qv;
        *(uint4*)&ks[t * QP + seg * 8] = kv;
        const __half* vh = (const __half*)&vv;
#pragma unroll
        for (int d = 0; d < 8; d++)
            vsT[(seg * 8 + d) * VP + t] = vh[d];
    }
    __syncthreads();

    const uint32_t qsa = smem_u32(qs);
    const uint32_t ksa = smem_u32(ks);
    const uint32_t vta = smem_u32(vsT);
    const int row_lo = 16 * wm + group;
    const int row_hi = row_lo + 8;

    // ---- QK^T: 8 j-tiles (j < 64), 2 k16 steps over d ----
    float sfrag[8][4];
#pragma unroll
    for (int jt = 0; jt < 8; jt++)
#pragma unroll
        for (int r = 0; r < 4; r++) sfrag[jt][r] = 0.f;

    const uint32_t a_addr0 = qsa + (uint32_t)((16 * wm + (lane & 15)) * QPB)
                           + ((uint32_t)(lane >> 4)) * 16;
    const uint32_t b_row  = (uint32_t)(8 * (lane >> 4) + (lane & 7));
    const uint32_t b_coff = ((uint32_t)((lane >> 3) & 1)) * 16;

#pragma unroll
    for (int k16 = 0; k16 < 2; k16++) {
        const uint32_t koff = (uint32_t)k16 * 32;
        uint32_t a0, a1, a2, a3;
        ldsm_x4(a0, a1, a2, a3, a_addr0 + koff);
        uint32_t bqk[8][2];
#pragma unroll
        for (int p = 0; p < 4; p++) {
            uint32_t addr = ksa + (uint32_t)((16 * p + b_row) * QPB) + b_coff + koff;
            ldsm_x4(bqk[2 * p][0], bqk[2 * p][1],
                    bqk[2 * p + 1][0], bqk[2 * p + 1][1], addr);
        }
#pragma unroll
        for (int jt = 0; jt < 8; jt++)
            mma_f16(sfrag[jt], a0, a1, a2, a3, bqk[jt][0], bqk[jt][1]);
    }

    // ---- softmax on fragments (mask cols/rows >= NT) ----
    float m_lo = -1e30f, m_hi = -1e30f;
#pragma unroll
    for (int jt = 0; jt < 8; jt++) {
        const int col0 = 8 * jt + 2 * tig;
#pragma unroll
        for (int r = 0; r < 4; r++) {
            const int col = col0 + (r & 1);
            const int row = (r < 2) ? row_lo : row_hi;
            float val;
            if (row < NT && col < NT)
                val = sfrag[jt][r] * SCALE + __ldg(&biasG[row * NT + col]);
            else
                val = -1e30f;
            sfrag[jt][r] = val;
            if (r < 2) m_lo = fmaxf(m_lo, val); else m_hi = fmaxf(m_hi, val);
        }
    }
    m_lo = fmaxf(m_lo, __shfl_xor_sync(0xffffffffu, m_lo, 1));
    m_lo = fmaxf(m_lo, __shfl_xor_sync(0xffffffffu, m_lo, 2));
    m_hi = fmaxf(m_hi, __shfl_xor_sync(0xffffffffu, m_hi, 1));
    m_hi = fmaxf(m_hi, __shfl_xor_sync(0xffffffffu, m_hi, 2));

    float s_lo = 0.f, s_hi = 0.f;
#pragma unroll
    for (int jt = 0; jt < 8; jt++) {
#pragma unroll
        for (int r = 0; r < 4; r++) {
            float e = __expf(sfrag[jt][r] - ((r < 2) ? m_lo : m_hi));
            sfrag[jt][r] = e;
            if (r < 2) s_lo += e; else s_hi += e;
        }
    }
    s_lo += __shfl_xor_sync(0xffffffffu, s_lo, 1);
    s_lo += __shfl_xor_sync(0xffffffffu, s_lo, 2);
    s_hi += __shfl_xor_sync(0xffffffffu, s_hi, 1);
    s_hi += __shfl_xor_sync(0xffffffffu, s_hi, 2);

    // ---- PV: P->A frags via half2 pack (no shuffles); B from vsT ----
    float o[4][4];
#pragma unroll
    for (int nt = 0; nt < 4; nt++)
#pragma unroll
        for (int r = 0; r < 4; r++) o[nt][r] = 0.f;

#pragma unroll
    for (int kt = 0; kt < 4; kt++) {
        const int jA = 2 * kt, jB = 2 * kt + 1;
        uint32_t a0 = pack_h2(sfrag[jA][0], sfrag[jA][1]);
        uint32_t a1 = pack_h2(sfrag[jA][2], sfrag[jA][3]);
        uint32_t a2 = pack_h2(sfrag[jB][0], sfrag[jB][1]);
        uint32_t a3 = pack_h2(sfrag[jB][2], sfrag[jB][3]);

        uint32_t bv[4][2];
#pragma unroll
        for (int dp = 0; dp < 2; dp++) {
            uint32_t addr = vta + (uint32_t)((16 * dp + b_row) * VPB)
                          + b_coff + (uint32_t)kt * 32;
            ldsm_x4(bv[2 * dp][0], bv[2 * dp][1],
                    bv[2 * dp + 1][0], bv[2 * dp + 1][1], addr);
        }
#pragma unroll
        for (int nt = 0; nt < 4; nt++)
            mma_f16(o[nt], a0, a1, a2, a3, bv[nt][0], bv[nt][1]);
    }

    // ---- store (divide by row sum), fp16 out for GEMM2 ----
    const float inv_lo = 1.f / s_lo;
    const float inv_hi = 1.f / s_hi;
    if (row_lo < NT) {
        __half* orow = &out[(size_t)rowbase[row_lo] * DIM + h * HD];
#pragma unroll
        for (int nt = 0; nt < 4; nt++)
            *(__half2*)&orow[8 * nt + 2 * tig] =
                __floats2half2_rn(o[nt][0] * inv_lo, o[nt][1] * inv_lo);
    }
    if (row_hi < NT) {
        __half* orow = &out[(size_t)rowbase[row_hi] * DIM + h * HD];
#pragma unroll
        for (int nt = 0; nt < 4; nt++)
            *(__half2*)&orow[8 * nt + 2 * tig] =
                __floats2half2_rn(o[nt][2] * inv_hi, o[nt][3] * inv_hi);
    }
}

// ---------------------------------------------------------------------------
extern "C" void kernel_launch(void* const* d_in, const int* in_sizes, int n_in,
                              void* d_out, int out_size)
{
    const float* x      = (const float*)d_in[0];
    const float* w_qkv  = (const float*)d_in[1];
    const float* w_out  = (const float*)d_in[2];
    const float* b_out  = (const float*)d_in[3];
    const float* pos    = (const float*)d_in[4];
    float* out = (float*)d_out;

    __half *qkv_ptr, *attn_ptr, *x16_ptr, *wqkvT_ptr, *woutT_ptr;
    float *bias_ptr;
    cudaGetSymbolAddress((void**)&qkv_ptr,  g_qkv);
    cudaGetSymbolAddress((void**)&attn_ptr, g_attn);
    cudaGetSymbolAddress((void**)&x16_ptr,  g_x16);
    cudaGetSymbolAddress((void**)&bias_ptr, g_bias);
    cudaGetSymbolAddress((void**)&wqkvT_ptr, g_wqkvT);
    cudaGetSymbolAddress((void**)&woutT_ptr, g_woutT);

    const int SMEM_BYTES = NSTAGE * STAGEB;   // 61440
    static bool attr_set = false;
    if (!attr_set) {
        cudaFuncSetAttribute(hgemm<true>,
            cudaFuncAttributeMaxDynamicSharedMemorySize, SMEM_BYTES);
        cudaFuncSetAttribute(hgemm<false>,
            cudaFuncAttributeMaxDynamicSharedMemorySize, SMEM_BYTES);
        attr_set = true;
    }

    // 0) prep
    bias_kernel<<<(NT * NT + 255) / 256, 256>>>(pos, bias_ptr);
    {
        dim3 blk(32, 32);
        transpose_kernel<<<dim3(QKV_N / 32, DIM / 32), blk>>>(w_qkv, wqkvT_ptr, DIM, QKV_N);
        transpose_kernel<<<dim3(DIM / 32, DIM / 32), blk>>>(w_out, woutT_ptr, DIM, DIM);
    }
    {
        int n4 = M_TOK * DIM / 4;
        f2h_kernel<<<(n4 + 255) / 256, 256>>>(x, x16_ptr, n4);
    }

    // 1) qkv = x @ w_qkv   (fp16 mma, fp16 out)
    {
        dim3 grid(QKV_N / 128, M_TOK / 128);
        hgemm<true><<<grid, 256, SMEM_BYTES>>>(x16_ptr, wqkvT_ptr, qkv_ptr, nullptr, QKV_N, DIM);
    }
    // 2) window attention (fp16 mma + ldmatrix)
    {
        dim3 grid(64, HEADS, 32);
        attn_kernel<<<grid, 128>>>(qkv_ptr, bias_ptr, attn_ptr);
    }
    // 3) out = attn @ w_out + b_out   (fp16 mma, fp32 out + bias)
    {
        dim3 grid(DIM / 128, M_TOK / 128);
        hgemm<false><<<grid, 256, SMEM_BYTES>>>(attn_ptr, woutT_ptr, out, b_out, DIM, DIM);
    }
}